// round 9
// baseline (speedup 1.0000x reference)
#include <cuda_runtime.h>
#include <cstdint>

// Problem constants (fixed by the dataset)
#define NN 50000
#define NE 1600000
#define NT 50
#define FDT 0.02f

// Geometry: one persistent block per SM
#define PBLK 148
#define THREADS 1024
#define NSEG 8
#define SEGN 6272                 // nodes per segment (8*6272 = 50176 >= NN)
#define NPAD (NSEG * SEGN)        // 50176 padded nodes
#define SEGB (SEGN * 16)          // 100352 bytes per segment buffer
#define ROWS_PB 338               // ceil(NN / PBLK)
#define M2 (NN * NSEG)            // 400000 (row,segment) buckets
#define CPB 2704                  // ceil(M2 / PBLK)
#define NBAR 64
#define SMEM_DYN (2 * SEGB + 64)  // two buffers + mbarriers

// ---------------- device scratch (static, no allocations) ----------------
__device__ float  g_r[2][NPAD * 4];     // rate tables, ping-pong, [node][batch], padded
__device__ float2 g_csr[NE];            // per edge: {weight, bitcast(smem byte offset of src)}
__device__ int    g_rso[M2 + 1];        // offsets per (row,segment) bucket
__device__ int    g_deg2[M2];
__device__ int    g_cur2[M2];
__device__ float  g_alpha[NN];
__device__ int    g_bars[NBAR];
__device__ int    g_part[PBLK];

// ---------------- init kernel (resets all mutable prep state each replay) ------
__global__ void init_kernel(const float* __restrict__ bias,
                            const float* __restrict__ tc) {
    int i = blockIdx.x * blockDim.x + threadIdx.x;
    if (i < NBAR) g_bars[i] = 0;
    if (i < M2) { g_deg2[i] = 0; g_cur2[i] = 0; }
    if (i < NN) {
        g_alpha[i] = FDT / fmaxf(tc[i], FDT);
        float rb = fmaxf(bias[i], 0.0f);
        *reinterpret_cast<float4*>(&g_r[0][4 * i]) = make_float4(rb, rb, rb, rb);
    }
}

// ---------------- barriers ----------------
__device__ __forceinline__ void full_barrier(int idx) {
    __threadfence();
    __syncthreads();
    if (threadIdx.x == 0) {
        atomicAdd(&g_bars[idx], 1);
        volatile int* p = &g_bars[idx];
        while (*p < PBLK) { __nanosleep(64); }
    }
    __syncthreads();
    __threadfence();
}

// No CCTL.IVALL: L1 keeps rso hot; cross-step data moves via L2 (st.cg/ld.cg/bulk).
__device__ __forceinline__ void light_barrier(int idx) {
    __syncthreads();
    if (threadIdx.x == 0) {
        int* a = &g_bars[idx];
        asm volatile("red.release.gpu.add.u32 [%0], 1;" :: "l"(a) : "memory");
        unsigned v;
        do {
            asm volatile("ld.relaxed.gpu.u32 %0, [%1];" : "=r"(v) : "l"(a));
            if (v < PBLK) __nanosleep(32);
        } while (v < PBLK);
        unsigned d;
        asm volatile("atom.acquire.gpu.add.u32 %0, [%1], 0;"
                     : "=r"(d) : "l"(a) : "memory");
    }
    __syncthreads();
}

// ---------------- mbarrier / bulk-copy helpers ----------------
__device__ __forceinline__ unsigned smem_u32(const void* p) {
    return (unsigned)__cvta_generic_to_shared(p);
}
__device__ __forceinline__ void mbar_init(unsigned mb) {
    asm volatile("mbarrier.init.shared.b64 [%0], 1;" :: "r"(mb) : "memory");
}
__device__ __forceinline__ void mbar_expect_tx(unsigned mb, unsigned bytes) {
    asm volatile("mbarrier.arrive.expect_tx.shared.b64 _, [%0], %1;"
                 :: "r"(mb), "r"(bytes) : "memory");
}
__device__ __forceinline__ void bulk_g2s(unsigned dst, const void* src,
                                         unsigned bytes, unsigned mb) {
    asm volatile("cp.async.bulk.shared::cta.global.mbarrier::complete_tx::bytes "
                 "[%0], [%1], %2, [%3];"
                 :: "r"(dst), "l"(src), "r"(bytes), "r"(mb) : "memory");
}
__device__ __forceinline__ void mbar_wait(unsigned mb, int phase) {
    asm volatile(
        "{\n\t.reg .pred P;\n\t"
        "WL%=:\n\t"
        "mbarrier.try_wait.parity.acquire.cta.shared::cta.b64 P, [%0], %1, 0x989680;\n\t"
        "@!P bra WL%=;\n\t}"
        :: "r"(mb), "r"((unsigned)phase) : "memory");
}

// ---------------- the whole problem in one persistent kernel ----------------
__global__ void __launch_bounds__(THREADS, 1)
net_kernel(const float* __restrict__ bias,
           const float* __restrict__ x,
           float* __restrict__ out,
           const int* __restrict__ src, const int* __restrict__ tgt,
           const float* __restrict__ sign, const float* __restrict__ cnt,
           const float* __restrict__ strg) {
    extern __shared__ __align__(16) char dsm[];
    const int tid = threadIdx.x;
    const int bid = blockIdx.x;

    // ---------- phase 1: (target,segment) histogram ----------
    for (int i = bid * THREADS + tid; i < NE; i += PBLK * THREADS) {
        int sseg = (unsigned)src[i] / SEGN;
        atomicAdd(&g_deg2[tgt[i] * NSEG + sseg], 1);
    }
    full_barrier(0);

    // ---------- phase 2: grid-wide exclusive scan of g_deg2 (M2 entries) ------
    {
        int* sc = (int*)dsm;                  // 1024 ints scratch
        __shared__ int s_red[32];
        __shared__ int s_off_sh;
        const int bstart = bid * CPB;
        const int e0 = tid * 3;
        const int j0 = bstart + e0;
        int d0 = 0, d1 = 0, d2 = 0;
        if (e0 < CPB && j0 < M2)         d0 = g_deg2[j0];
        if (e0 + 1 < CPB && j0 + 1 < M2) d1 = g_deg2[j0 + 1];
        if (e0 + 2 < CPB && j0 + 2 < M2) d2 = g_deg2[j0 + 2];
        int tsum = d0 + d1 + d2;
        sc[tid] = tsum;
        __syncthreads();
        for (int o = 1; o < THREADS; o <<= 1) {
            int v = (tid >= o) ? sc[tid - o] : 0;
            __syncthreads();
            sc[tid] += v;
            __syncthreads();
        }
        const int incl = sc[tid];
        const int btot = sc[THREADS - 1];
        if (tid == 0) g_part[bid] = btot;
        full_barrier(1);
        {
            int acc = (tid < bid) ? g_part[tid] : 0;
            #pragma unroll
            for (int o = 16; o; o >>= 1) acc += __shfl_xor_sync(0xffffffffu, acc, o);
            if ((tid & 31) == 0) s_red[tid >> 5] = acc;
            __syncthreads();
            if (tid == 0) {
                int s = 0;
                #pragma unroll
                for (int w = 0; w < 32; w++) s += s_red[w];
                s_off_sh = s;
            }
            __syncthreads();
        }
        const int p = s_off_sh + incl - tsum;
        if (e0 < CPB && j0 < M2)         g_rso[j0] = p;
        if (e0 + 1 < CPB && j0 + 1 < M2) g_rso[j0 + 1] = p + d0;
        if (e0 + 2 < CPB && j0 + 2 < M2) g_rso[j0 + 2] = p + d0 + d1;
        if (bid == PBLK - 1 && tid == 0) g_rso[M2] = s_off_sh + btot;
    }
    full_barrier(2);

    // ---------- phase 3: scatter edges into (row,segment) buckets ----------
    for (int i = bid * THREADS + tid; i < NE; i += PBLK * THREADS) {
        float w = sign[i] * fmaxf(cnt[i], 0.0f) * fmaxf(strg[i], 0.0f);
        int s_ = src[i];
        int sseg = (unsigned)s_ / SEGN;
        int idx = tgt[i] * NSEG + sseg;
        int pos = atomicAdd(&g_cur2[idx], 1);
        int off = (s_ - sseg * SEGN) * 16;            // byte offset within segment buffer
        g_csr[g_rso[idx] + pos] = make_float2(w, __int_as_float(off));
    }
    full_barrier(3);

    // ---------- phase 4: 50 recurrent steps ----------
    const unsigned buf_a0 = smem_u32(dsm);
    const unsigned buf_a1 = smem_u32(dsm + SEGB);
    const unsigned mb0 = smem_u32(dsm + 2 * SEGB);
    const unsigned mb1 = mb0 + 8;
    if (tid == 0) {
        mbar_init(mb0);
        mbar_init(mb1);
        asm volatile("fence.proxy.async.shared::cta;" ::: "memory");
    }
    __syncthreads();

    const int gidx = tid >> 2;                       // 0..255 group per block
    const int lig = tid & 3;                         // lane in group == batch id
    const unsigned gmask = 0xFu << ((tid & 31) & ~3u);
    const int rowbase = bid * ROWS_PB;
    const int nrows = (NN - rowbase < ROWS_PB) ? (NN - rowbase) : ROWS_PB;
    const bool v0 = gidx < nrows;
    const bool v1 = (256 + gidx) < nrows;
    const int r0 = v0 ? rowbase + gidx : rowbase;
    const int r1 = v1 ? rowbase + 256 + gidx : rowbase;
    const float bi0 = v0 ? __ldg(&bias[r0]) : 0.0f;
    const float bi1 = v1 ? __ldg(&bias[r1]) : 0.0f;
    const float al0 = v0 ? g_alpha[r0] : 0.0f;
    const float al1 = v1 ? g_alpha[r1] : 0.0f;
    float vb0 = bi0, vb1 = bi1;
    const int base0 = r0 * NSEG, base1 = r1 * NSEG;
    int ph0 = 0, ph1 = 0;

    for (int t = 0; t < NT; t++) {
        const char* table = (const char*)g_r[t & 1];
        float* __restrict__ rnew = g_r[(t & 1) ^ 1];

        if (tid == 0) {
            asm volatile("fence.proxy.async;" ::: "memory");
            mbar_expect_tx(mb0, SEGB);
            bulk_g2s(buf_a0, table, SEGB, mb0);               // seg 0
            mbar_expect_tx(mb1, SEGB);
            bulk_g2s(buf_a1, table + SEGB, SEGB, mb1);        // seg 1
        }
        float xv0 = v0 ? __ldcg(&x[(lig * NT + t) * NN + r0]) : 0.0f;
        float xv1 = v1 ? __ldcg(&x[(lig * NT + t) * NN + r1]) : 0.0f;

        float a0x = 0.f, a0y = 0.f, a0z = 0.f, a0w = 0.f;
        float a1x = 0.f, a1y = 0.f, a1z = 0.f, a1w = 0.f;

        for (int seg = 0; seg < NSEG; seg++) {
            const int b = seg & 1;
            if (tid < 32) mbar_wait(b ? mb1 : mb0, b ? ph1 : ph0);
            __syncthreads();                                  // fill visible; prev seg done

            const char* sb = b ? (dsm + SEGB) : dsm;
            if (v0) {
                int s_ = __ldg(&g_rso[base0 + seg]);
                int e_ = __ldg(&g_rso[base0 + seg + 1]);
                for (int i = s_ + lig; i < e_; i += 4) {
                    float2 ed = __ldcg(&g_csr[i]);
                    const float4 rr = *reinterpret_cast<const float4*>(
                        sb + __float_as_int(ed.y));
                    a0x = fmaf(rr.x, ed.x, a0x);
                    a0y = fmaf(rr.y, ed.x, a0y);
                    a0z = fmaf(rr.z, ed.x, a0z);
                    a0w = fmaf(rr.w, ed.x, a0w);
                }
            }
            if (v1) {
                int s_ = __ldg(&g_rso[base1 + seg]);
                int e_ = __ldg(&g_rso[base1 + seg + 1]);
                for (int i = s_ + lig; i < e_; i += 4) {
                    float2 ed = __ldcg(&g_csr[i]);
                    const float4 rr = *reinterpret_cast<const float4*>(
                        sb + __float_as_int(ed.y));
                    a1x = fmaf(rr.x, ed.x, a1x);
                    a1y = fmaf(rr.y, ed.x, a1y);
                    a1z = fmaf(rr.z, ed.x, a1z);
                    a1w = fmaf(rr.w, ed.x, a1w);
                }
            }
            __syncthreads();                                  // all done with buf b
            if (tid == 0 && seg + 2 < NSEG) {                 // refill freed buffer
                asm volatile("fence.proxy.async.shared::cta;" ::: "memory");
                unsigned mb = b ? mb1 : mb0;
                unsigned ba = b ? buf_a1 : buf_a0;
                mbar_expect_tx(mb, SEGB);
                bulk_g2s(ba, table + (size_t)(seg + 2) * SEGB, SEGB, mb);
            }
            if (b) ph1 ^= 1; else ph0 ^= 1;
        }

        // reduce within 4-lane groups (butterfly leaves totals in all lanes)
        #pragma unroll
        for (int o = 2; o; o >>= 1) {
            a0x += __shfl_xor_sync(gmask, a0x, o, 4);
            a0y += __shfl_xor_sync(gmask, a0y, o, 4);
            a0z += __shfl_xor_sync(gmask, a0z, o, 4);
            a0w += __shfl_xor_sync(gmask, a0w, o, 4);
            a1x += __shfl_xor_sync(gmask, a1x, o, 4);
            a1y += __shfl_xor_sync(gmask, a1y, o, 4);
            a1z += __shfl_xor_sync(gmask, a1z, o, 4);
            a1w += __shfl_xor_sync(gmask, a1w, o, 4);
        }
        if (v0) {
            float sum = (lig == 0) ? a0x : (lig == 1) ? a0y : (lig == 2) ? a0z : a0w;
            float vn = fmaf(al0, bi0 - vb0 + sum + xv0, vb0);
            vb0 = vn;
            float rn = fmaxf(vn, 0.f);
            __stcg(&rnew[4 * r0 + lig], rn);
            __stcs(&out[(lig * NT + t) * NN + r0], rn);
        }
        if (v1) {
            float sum = (lig == 0) ? a1x : (lig == 1) ? a1y : (lig == 2) ? a1z : a1w;
            float vn = fmaf(al1, bi1 - vb1 + sum + xv1, vb1);
            vb1 = vn;
            float rn = fmaxf(vn, 0.f);
            __stcg(&rnew[4 * r1 + lig], rn);
            __stcs(&out[(lig * NT + t) * NN + r1], rn);
        }

        if (t != NT - 1) light_barrier(4 + t);
    }
}

// ---------------- launch ----------------
extern "C" void kernel_launch(void* const* d_in, const int* in_sizes, int n_in,
                              void* d_out, int out_size) {
    const float* x      = (const float*)d_in[0];  // [B,T,N]
    const float* bias   = (const float*)d_in[1];  // [N]
    const float* tcst   = (const float*)d_in[2];  // [N]
    const float* sign   = (const float*)d_in[3];  // [E]
    const float* cnt    = (const float*)d_in[4];  // [E]
    const float* strg   = (const float*)d_in[5];  // [E]
    const int*   srcidx = (const int*)d_in[6];    // [E]
    const int*   tgtidx = (const int*)d_in[7];    // [E]
    float* out = (float*)d_out;                   // [B,T,N]

    cudaFuncSetAttribute(net_kernel,
                         cudaFuncAttributeMaxDynamicSharedMemorySize, SMEM_DYN);

    init_kernel<<<(M2 + 255) / 256, 256>>>(bias, tcst);
    net_kernel<<<PBLK, THREADS, SMEM_DYN>>>(bias, x, out,
                                            srcidx, tgtidx, sign, cnt, strg);

    (void)in_sizes; (void)n_in; (void)out_size;
}

// round 12
// speedup vs baseline: 1.1706x; 1.1706x over previous
#include <cuda_runtime.h>
#include <cstdint>

// Problem constants (fixed by the dataset)
#define NN 50000
#define NE 1600000
#define NT 50
#define FDT 0.02f

// Persistent-kernel geometry: 296 = 148 SMs * 2 blocks (proven R3/R5 geometry)
#define PBLK 296
#define THREADS 512
#define GPB (THREADS / 4)           // 128 groups of 4 lanes per block
#define NGROUPS (PBLK * GPB)        // 37888 groups
#define MAXK 2                      // ceil(NN / NGROUPS) rows per group
#define M2 (2 * NN)                 // buckets: [0,NN) gather-by-target, [NN,2NN) RED-by-source
#define CHUNK 338                   // ceil(M2 / PBLK) for the grid scan
#define NBAR 64

// Edge split: ~56% gather half (L1tex pipe), ~44% RED half (LTS atomic ALU)
#define IS_GATHER(i) (((i) & 15) < 9)

// ---------------- device scratch (static, no allocations) ----------------
__device__ float2 g_csr[NE];            // gather half: {w, bits(src)}; RED half: {w, bits(tgt)}
__device__ int    g_rso[M2 + 1];
__device__ int    g_deg[M2];
__device__ int    g_cur[M2];
__device__ float  g_r[2][NN * 4];       // rate tables, ping-pong, [node][batch]
__device__ float  g_acc[2][NN * 4];     // RED accumulators, double-buffered
__device__ float  g_alpha[NN];
__device__ int    g_bars[NBAR];
__device__ int    g_part[PBLK];

__device__ __forceinline__ void red_v4(float* p, float a, float b, float c, float d) {
    asm volatile("red.global.add.v4.f32 [%0], {%1, %2, %3, %4};"
                 :: "l"(p), "f"(a), "f"(b), "f"(c), "f"(d) : "memory");
}

// ---------------- init kernel (resets all mutable state each graph replay) ------
__global__ void init_kernel(const float* __restrict__ bias,
                            const float* __restrict__ tc) {
    int i = blockIdx.x * blockDim.x + threadIdx.x;
    if (i < NBAR) g_bars[i] = 0;
    if (i < M2) { g_deg[i] = 0; g_cur[i] = 0; }
    if (i < NN) {
        g_alpha[i] = FDT / fmaxf(tc[i], FDT);
        float rb = fmaxf(bias[i], 0.0f);
        *reinterpret_cast<float4*>(&g_r[0][4 * i]) = make_float4(rb, rb, rb, rb);
        float4 z = make_float4(0.f, 0.f, 0.f, 0.f);
        *reinterpret_cast<float4*>(&g_acc[0][4 * i]) = z;
        *reinterpret_cast<float4*>(&g_acc[1][4 * i]) = z;
    }
}

// ---------------- barriers ----------------
__device__ __forceinline__ void full_barrier(int idx) {
    __threadfence();
    __syncthreads();
    if (threadIdx.x == 0) {
        atomicAdd(&g_bars[idx], 1);
        volatile int* p = &g_bars[idx];
        while (*p < PBLK) { __nanosleep(64); }
    }
    __syncthreads();
    __threadfence();
}

// No CCTL.IVALL: L1 keeps edge lists hot; cross-step data moves via L2
// (st.cg/ld.cg/red.global). Release orders prior relaxed REDs; acquire pairs it.
__device__ __forceinline__ void light_barrier(int idx) {
    __syncthreads();
    if (threadIdx.x == 0) {
        int* a = &g_bars[idx];
        asm volatile("red.release.gpu.add.u32 [%0], 1;" :: "l"(a) : "memory");
        unsigned v;
        do {
            asm volatile("ld.relaxed.gpu.u32 %0, [%1];" : "=r"(v) : "l"(a));
            if (v < PBLK) __nanosleep(32);
        } while (v < PBLK);
        unsigned d;
        asm volatile("atom.acquire.gpu.add.u32 %0, [%1], 0;"
                     : "=r"(d) : "l"(a) : "memory");
    }
    __syncthreads();
}

// ---------------- the whole problem in one persistent kernel ----------------
__global__ void __launch_bounds__(THREADS, 2)
net_kernel(const float* __restrict__ bias,
           const float* __restrict__ x,
           float* __restrict__ out,
           const int* __restrict__ src, const int* __restrict__ tgt,
           const float* __restrict__ sign, const float* __restrict__ cnt,
           const float* __restrict__ strg) {
    const int tid = threadIdx.x;
    const int bid = blockIdx.x;

    // ---------- phase 1: bucket histogram ----------
    for (int i = bid * THREADS + tid; i < NE; i += PBLK * THREADS) {
        int b_ = IS_GATHER(i) ? tgt[i] : NN + src[i];
        atomicAdd(&g_deg[b_], 1);
    }
    full_barrier(0);

    // ---------- phase 2: grid-wide exclusive scan of g_deg (M2 entries) ----------
    {
        __shared__ int s_scan[THREADS];
        __shared__ int s_off;
        const int cbase = bid * CHUNK;
        // Each thread covers CHUNK/THREADS... simpler: serial-in-thread over
        // ceil(CHUNK/THREADS)=1 slot (CHUNK=338 <= THREADS=512): one per thread.
        int n = M2 - cbase;
        if (n > CHUNK) n = CHUNK;
        if (n < 0) n = 0;
        int dval = (tid < n) ? g_deg[cbase + tid] : 0;
        s_scan[tid] = dval;
        __syncthreads();
        #pragma unroll
        for (int o = 1; o < THREADS; o <<= 1) {
            int v = (tid >= o) ? s_scan[tid - o] : 0;
            __syncthreads();
            s_scan[tid] += v;
            __syncthreads();
        }
        if (tid == 0) g_part[bid] = s_scan[THREADS - 1];
        full_barrier(1);
        {
            __shared__ int s_red[16];
            int acc = (tid < bid) ? g_part[tid] : 0;
            #pragma unroll
            for (int o = 16; o; o >>= 1) acc += __shfl_xor_sync(0xffffffffu, acc, o);
            if ((tid & 31) == 0) s_red[tid >> 5] = acc;
            __syncthreads();
            if (tid == 0) {
                int s = 0;
                #pragma unroll
                for (int w = 0; w < 16; w++) s += s_red[w];
                s_off = s;
            }
            __syncthreads();
        }
        if (tid < n) g_rso[cbase + tid] = s_off + s_scan[tid] - dval;
        if (bid == PBLK - 1 && tid == 0) g_rso[M2] = s_off + s_scan[THREADS - 1];
    }
    full_barrier(2);

    // ---------- phase 3: scatter edges into buckets ----------
    for (int i = bid * THREADS + tid; i < NE; i += PBLK * THREADS) {
        float w = sign[i] * fmaxf(cnt[i], 0.0f) * fmaxf(strg[i], 0.0f);
        int b_, other;
        if (IS_GATHER(i)) { b_ = tgt[i];      other = src[i]; }
        else              { b_ = NN + src[i]; other = tgt[i]; }
        int pos = atomicAdd(&g_cur[b_], 1);
        g_csr[g_rso[b_] + pos] = make_float2(w, __int_as_float(other));
    }
    full_barrier(3);

    // ---------- phase 4: 50 recurrent steps, gather + RED halves overlapped ------
    const int gid = bid * GPB + (tid >> 2);          // 4-lane group id
    const int lig = tid & 3;                         // lane in group == batch id
    const unsigned gmask = 0xFu << ((tid & 31) & ~3u);

    int   rows[MAXK], gs[MAXK], ge[MAXK], ssb[MAXK], seb[MAXK];
    bool  val[MAXK];
    float bi[MAXK], al[MAXK], vb[MAXK];
    #pragma unroll
    for (int k = 0; k < MAXK; k++) {
        int r = gid + k * NGROUPS;
        bool o_ = r < NN;
        val[k] = o_;
        rows[k] = o_ ? r : 0;
        gs[k]  = o_ ? g_rso[rows[k]] : 0;
        ge[k]  = o_ ? g_rso[rows[k] + 1] : 0;
        ssb[k] = o_ ? g_rso[NN + rows[k]] : 0;
        seb[k] = o_ ? g_rso[NN + rows[k] + 1] : 0;
        bi[k]  = o_ ? __ldg(&bias[rows[k]]) : 0.0f;
        al[k]  = o_ ? g_alpha[rows[k]] : 0.0f;
        vb[k]  = bi[k];                              // v starts at bias
    }

    // prologue: RED-scatter r0 = relu(bias) into acc[0]
    #pragma unroll
    for (int k = 0; k < MAXK; k++) {
        float r0v = fmaxf(bi[k], 0.0f);
        for (int j = ssb[k] + lig; j < seb[k]; j += 4) {
            float2 ed = g_csr[j];
            float m = r0v * ed.x;
            red_v4(&g_acc[0][4 * __float_as_int(ed.y)], m, m, m, m);
        }
    }
    light_barrier(62);

    for (int t = 0; t < NT; t++) {
        const float* __restrict__ rates = g_r[t & 1];
        float* __restrict__       rnew  = g_r[(t & 1) ^ 1];
        float* __restrict__       acc_c = g_acc[t & 1];
        float* __restrict__       acc_n = g_acc[(t & 1) ^ 1];

        #pragma unroll
        for (int k = 0; k < MAXK; k++) {
            float xv = val[k] ? __ldcg(&x[(lig * NT + t) * NN + rows[k]]) : 0.0f;

            // gather half (L1tex pipe)
            float ax = 0.f, ay = 0.f, az = 0.f, aw = 0.f;
            int i = gs[k] + lig;
            for (; i + 4 < ge[k]; i += 8) {
                float2 p0 = g_csr[i];                // L1-resident across steps
                float2 p1 = g_csr[i + 4];
                float4 r0 = __ldcg(reinterpret_cast<const float4*>(
                                       rates + 4 * __float_as_int(p0.y)));
                float4 r1 = __ldcg(reinterpret_cast<const float4*>(
                                       rates + 4 * __float_as_int(p1.y)));
                ax = fmaf(r0.x, p0.x, ax); ay = fmaf(r0.y, p0.x, ay);
                az = fmaf(r0.z, p0.x, az); aw = fmaf(r0.w, p0.x, aw);
                ax = fmaf(r1.x, p1.x, ax); ay = fmaf(r1.y, p1.x, ay);
                az = fmaf(r1.z, p1.x, az); aw = fmaf(r1.w, p1.x, aw);
            }
            if (i < ge[k]) {
                float2 p0 = g_csr[i];
                float4 r0 = __ldcg(reinterpret_cast<const float4*>(
                                       rates + 4 * __float_as_int(p0.y)));
                ax = fmaf(r0.x, p0.x, ax); ay = fmaf(r0.y, p0.x, ay);
                az = fmaf(r0.z, p0.x, az); aw = fmaf(r0.w, p0.x, aw);
            }
            #pragma unroll
            for (int o = 2; o; o >>= 1) {
                ax += __shfl_xor_sync(gmask, ax, o, 4);
                ay += __shfl_xor_sync(gmask, ay, o, 4);
                az += __shfl_xor_sync(gmask, az, o, 4);
                aw += __shfl_xor_sync(gmask, aw, o, 4);
            }

            float rn = 0.0f;
            if (val[k]) {
                float sum = (lig == 0) ? ax : (lig == 1) ? ay : (lig == 2) ? az : aw;
                sum += __ldcg(&acc_c[4 * rows[k] + lig]);   // RED half of sum_t
                float vn = fmaf(al[k], bi[k] - vb[k] + sum + xv, vb[k]);
                vb[k] = vn;
                rn = fmaxf(vn, 0.f);
                __stcg(&acc_c[4 * rows[k] + lig], 0.0f);    // clear for reuse at t+2
                __stcg(&rnew[4 * rows[k] + lig], rn);
                __stcs(&out[(lig * NT + t) * NN + rows[k]], rn);
            }

            if (t != NT - 1) {
                // RED half for step t+1 (register-resident source rates)
                float rn0 = __shfl_sync(gmask, rn, 0, 4);
                float rn1 = __shfl_sync(gmask, rn, 1, 4);
                float rn2 = __shfl_sync(gmask, rn, 2, 4);
                float rn3 = __shfl_sync(gmask, rn, 3, 4);
                for (int j = ssb[k] + lig; j < seb[k]; j += 4) {
                    float2 ed = g_csr[j];
                    int tg = __float_as_int(ed.y);
                    red_v4(&acc_n[4 * tg],
                           rn0 * ed.x, rn1 * ed.x, rn2 * ed.x, rn3 * ed.x);
                }
            }
        }

        if (t != NT - 1) light_barrier(4 + t);
    }
}

// ---------------- launch ----------------
extern "C" void kernel_launch(void* const* d_in, const int* in_sizes, int n_in,
                              void* d_out, int out_size) {
    const float* x      = (const float*)d_in[0];  // [B,T,N]
    const float* bias   = (const float*)d_in[1];  // [N]
    const float* tcst   = (const float*)d_in[2];  // [N]
    const float* sign   = (const float*)d_in[3];  // [E]
    const float* cnt    = (const float*)d_in[4];  // [E]
    const float* strg   = (const float*)d_in[5];  // [E]
    const int*   srcidx = (const int*)d_in[6];    // [E]
    const int*   tgtidx = (const int*)d_in[7];    // [E]
    float* out = (float*)d_out;                   // [B,T,N]

    init_kernel<<<(M2 + 255) / 256, 256>>>(bias, tcst);
    net_kernel<<<PBLK, THREADS>>>(bias, x, out, srcidx, tgtidx, sign, cnt, strg);

    (void)in_sizes; (void)n_in; (void)out_size;
}

// round 13
// speedup vs baseline: 1.9885x; 1.6987x over previous
#include <cuda_runtime.h>
#include <cuda_bf16.h>
#include <cstdint>

// Problem constants (fixed by the dataset)
#define NN 50000
#define NE 1600000
#define NT 50
#define FDT 0.02f

// Persistent-kernel geometry: 444 = 148 SMs * 3 blocks, co-resident at <=40 regs
#define PBLK 444
#define THREADS 512
#define GPB (THREADS / 4)           // 128 groups of 4 lanes per block
#define NGROUPS (PBLK * GPB)        // 56832 >= NN -> exactly one row per group
#define CHUNK 113                   // ceil(NN / PBLK) for the grid scan
#define NBAR 64

// ---------------- device scratch (static, no allocations) ----------------
__device__ float2 g_csr[NE];            // per edge: {weight, bitcast(src)} sorted by TARGET
__device__ int    g_pos[NE];            // per edge: slot within its target row (from hist)
__device__ int    g_row_start[NN + 1];
__device__ int    g_deg[NN];
__device__ float  g_r[2][NN * 4];       // rate tables, ping-pong, [node][batch]
__device__ float  g_alpha[NN];
__device__ int    g_bars[NBAR];         // per-barrier arrival counters (reset by init)
__device__ int    g_part[PBLK];         // scan partials

// ---------------- init kernel (resets barrier state each graph replay) ----------
__global__ void init_kernel(const float* __restrict__ bias,
                            const float* __restrict__ tc) {
    int i = blockIdx.x * blockDim.x + threadIdx.x;
    if (i < NBAR) g_bars[i] = 0;
    if (i < NN) {
        g_deg[i] = 0;
        g_alpha[i] = FDT / fmaxf(tc[i], FDT);
        float rb = fmaxf(bias[i], 0.0f);
        *reinterpret_cast<float4*>(&g_r[0][4 * i]) = make_float4(rb, rb, rb, rb);
    }
}

// ---------------- barriers ----------------
// Full barrier (prep phases): fences + L1 invalidate on both sides.
__device__ __forceinline__ void full_barrier(int idx) {
    __threadfence();
    __syncthreads();
    if (threadIdx.x == 0) {
        atomicAdd(&g_bars[idx], 1);
        volatile int* p = &g_bars[idx];
        while (*p < PBLK) { __nanosleep(64); }
    }
    __syncthreads();
    __threadfence();                    // acquire-side invalidate
}

// Light barrier (step loop): scoped release/acquire atomics, NO CCTL.IVALL,
// so the L1-resident CSR survives. All cross-step mutable data moves via
// ld.cg/st.cg (L2-only), so skipping the L1 invalidate is safe. This is the
// cooperative-groups grid.sync() pattern (morally strong via bar.sync chain).
__device__ __forceinline__ void light_barrier(int idx) {
    __syncthreads();
    if (threadIdx.x == 0) {
        int* a = &g_bars[idx];
        asm volatile("red.release.gpu.add.u32 [%0], 1;" :: "l"(a) : "memory");
        unsigned v;
        do {
            asm volatile("ld.relaxed.gpu.u32 %0, [%1];" : "=r"(v) : "l"(a));
            if (v < PBLK) __nanosleep(32);
        } while (v < PBLK);
        unsigned d;
        asm volatile("atom.acquire.gpu.add.u32 %0, [%1], 0;"
                     : "=r"(d) : "l"(a) : "memory");
    }
    __syncthreads();
}

// ---------------- the whole problem in one persistent kernel ----------------
__global__ void __launch_bounds__(THREADS, 3)
net_kernel(const float* __restrict__ bias,
           const float* __restrict__ x,
           float* __restrict__ out,
           const int* __restrict__ src, const int* __restrict__ tgt,
           const float* __restrict__ sign, const float* __restrict__ cnt,
           const float* __restrict__ strg) {
    const int tid = threadIdx.x;
    const int bid = blockIdx.x;

    // ---------- phase 1: degree histogram (by target); atomic also yields slot ----
    for (int i = bid * THREADS + tid; i < NE; i += PBLK * THREADS) {
        g_pos[i] = atomicAdd(&g_deg[tgt[i]], 1);
    }
    full_barrier(0);

    // ---------- phase 2: grid-wide exclusive scan of g_deg ----------
    {
        __shared__ int s_scan[THREADS];
        __shared__ int s_off;
        const int cbase = bid * CHUNK;
        int n = NN - cbase;
        if (n > CHUNK) n = CHUNK;
        if (n < 0) n = 0;
        int dval = (tid < n) ? g_deg[cbase + tid] : 0;
        s_scan[tid] = dval;
        __syncthreads();
        #pragma unroll
        for (int o = 1; o < THREADS; o <<= 1) {
            int v = (tid >= o) ? s_scan[tid - o] : 0;
            __syncthreads();
            s_scan[tid] += v;
            __syncthreads();
        }
        if (tid == 0) g_part[bid] = s_scan[THREADS - 1];
        full_barrier(1);
        {
            __shared__ int s_red[16];
            int acc = 0;
            for (int j = tid; j < bid; j += THREADS) acc += g_part[j];
            #pragma unroll
            for (int o = 16; o; o >>= 1) acc += __shfl_xor_sync(0xffffffffu, acc, o);
            if ((tid & 31) == 0) s_red[tid >> 5] = acc;
            __syncthreads();
            if (tid == 0) {
                int s = 0;
                #pragma unroll
                for (int w = 0; w < 16; w++) s += s_red[w];
                s_off = s;
            }
            __syncthreads();
        }
        if (tid < n) g_row_start[cbase + tid] = s_off + s_scan[tid] - dval;
        if (bid == PBLK - 1 && tid == 0) g_row_start[NN] = s_off + s_scan[THREADS - 1];
    }
    full_barrier(2);

    // ---------- phase 3: scatter edges into target-sorted CSR (atomic-free) ------
    for (int i = bid * THREADS + tid; i < NE; i += PBLK * THREADS) {
        float w = sign[i] * fmaxf(cnt[i], 0.0f) * fmaxf(strg[i], 0.0f);
        int t_ = tgt[i];
        g_csr[g_row_start[t_] + g_pos[i]] = make_float2(w, __int_as_float(src[i]));
    }
    full_barrier(3);

    // ---------- phase 4: 50 recurrent steps ----------
    const int gid = bid * GPB + (tid >> 2);          // one row per 4-lane group
    const int lig = tid & 3;                         // lane in group == batch id
    const unsigned gmask = 0xFu << ((tid & 31) & ~3u);

    const bool ok = gid < NN;
    const int row = ok ? gid : 0;
    const int rs = ok ? g_row_start[row] : 0;
    const int re = ok ? g_row_start[row + 1] : 0;
    const float bi = ok ? __ldg(&bias[row]) : 0.0f;
    const float al = ok ? g_alpha[row] : 0.0f;
    float vb = bi;                                   // v starts at bias
    const float* xp = x + (size_t)lig * NT * NN + row;
    float*       op = out + (size_t)lig * NT * NN + row;

    for (int t = 0; t < NT; t++) {
        const float* __restrict__ rates = g_r[t & 1];
        float* __restrict__       rnew  = g_r[(t & 1) ^ 1];

        float xv = ok ? __ldcg(xp) : 0.0f;

        float ax = 0.f, ay = 0.f, az = 0.f, aw = 0.f;
        int i = rs + lig;
        for (; i + 4 < re; i += 8) {                 // 2 edges per lane per iter
            float2 p0 = g_csr[i];                    // L1-resident across steps
            float2 p1 = g_csr[i + 4];
            float4 r0 = __ldcg(reinterpret_cast<const float4*>(
                                   rates + 4 * __float_as_int(p0.y)));
            float4 r1 = __ldcg(reinterpret_cast<const float4*>(
                                   rates + 4 * __float_as_int(p1.y)));
            ax = fmaf(r0.x, p0.x, ax);
            ay = fmaf(r0.y, p0.x, ay);
            az = fmaf(r0.z, p0.x, az);
            aw = fmaf(r0.w, p0.x, aw);
            ax = fmaf(r1.x, p1.x, ax);
            ay = fmaf(r1.y, p1.x, ay);
            az = fmaf(r1.z, p1.x, az);
            aw = fmaf(r1.w, p1.x, aw);
        }
        if (i < re) {
            float2 p0 = g_csr[i];
            float4 r0 = __ldcg(reinterpret_cast<const float4*>(
                                   rates + 4 * __float_as_int(p0.y)));
            ax = fmaf(r0.x, p0.x, ax);
            ay = fmaf(r0.y, p0.x, ay);
            az = fmaf(r0.z, p0.x, az);
            aw = fmaf(r0.w, p0.x, aw);
        }
        // reduce within the 4-lane group
        #pragma unroll
        for (int o = 2; o; o >>= 1) {
            ax += __shfl_xor_sync(gmask, ax, o, 4);
            ay += __shfl_xor_sync(gmask, ay, o, 4);
            az += __shfl_xor_sync(gmask, az, o, 4);
            aw += __shfl_xor_sync(gmask, aw, o, 4);
        }
        if (ok) {
            float sum = (lig == 0) ? ax : (lig == 1) ? ay : (lig == 2) ? az : aw;
            float vn = fmaf(al, bi - vb + sum + xv, vb);
            vb = vn;
            float rn = fmaxf(vn, 0.f);
            __stcg(&rnew[4 * row + lig], rn);        // L2-only: no stale L1 copies
            __stcs(op, rn);
        }
        xp += NN;
        op += NN;

        if (t != NT - 1) light_barrier(4 + t);
    }
}

// ---------------- launch ----------------
extern "C" void kernel_launch(void* const* d_in, const int* in_sizes, int n_in,
                              void* d_out, int out_size) {
    const float* x      = (const float*)d_in[0];  // [B,T,N]
    const float* bias   = (const float*)d_in[1];  // [N]
    const float* tcst   = (const float*)d_in[2];  // [N]
    const float* sign   = (const float*)d_in[3];  // [E]
    const float* cnt    = (const float*)d_in[4];  // [E]
    const float* strg   = (const float*)d_in[5];  // [E]
    const int*   srcidx = (const int*)d_in[6];    // [E]
    const int*   tgtidx = (const int*)d_in[7];    // [E]
    float* out = (float*)d_out;                   // [B,T,N]

    const int nblk = (NN + 255) / 256;
    init_kernel<<<nblk, 256>>>(bias, tcst);
    net_kernel<<<PBLK, THREADS>>>(bias, x, out, srcidx, tgtidx, sign, cnt, strg);

    (void)in_sizes; (void)n_in; (void)out_size;
}